// round 6
// baseline (speedup 1.0000x reference)
#include <cuda_runtime.h>
#include <math_constants.h>

#define NN 50000
#define EE 500000
#define FF 64
#define HH 4
#define HF 256          // H*F
#define EDIM 64
#define ET (EE + NN)    // 550000 edges incl. self loops (550000 = 34375 * 16 exactly)

typedef unsigned long long u64;

// ---------------- scratch (device globals; no allocation allowed) ----------------
__device__ float  g_xl[NN * HF];        // x @ W_l + b_l
__device__ float  g_xr[NN * HF];        // x @ W_r + b_r
__device__ float  g_lattr[NN * EDIM];   // self-loop edge attr sums
__device__ float  g_cnt[NN];
__device__ u64    g_Wp[32 * HF];        // We packed over k-pairs: (We[2kp][j], We[2kp+1][j])
__device__ float  g_alpha[ET * HH];     // pre-softmax logits, then exp()
__device__ float  g_amax[NN * HH];
__device__ float  g_denom[NN * HH];
__device__ float  g_out[NN * FF];       // head-summed aggregate, then y
__device__ double g_bsum[FF];
__device__ double g_bsq[FF];
__device__ float  g_mean[FF];
__device__ float  g_istd[FF];

// ---------------- helpers ----------------
__device__ __forceinline__ void atomicMaxF(float* addr, float v) {
    if (v >= 0.0f) atomicMax((int*)addr, __float_as_int(v));
    else           atomicMin((unsigned int*)addr, __float_as_uint(v));
}
__device__ __forceinline__ u64 pack2(float lo, float hi) {
    u64 r; asm("mov.b64 %0, {%1, %2};" : "=l"(r) : "f"(lo), "f"(hi)); return r;
}
__device__ __forceinline__ float2 unpack2(u64 v) {
    float2 r; asm("mov.b64 {%0, %1}, %2;" : "=f"(r.x), "=f"(r.y) : "l"(v)); return r;
}
__device__ __forceinline__ u64 ffma2(u64 a, u64 b, u64 c) {
    u64 d; asm("fma.rn.f32x2 %0, %1, %2, %3;" : "=l"(d) : "l"(a), "l"(b), "l"(c)); return d;
}
__device__ __forceinline__ void red4(float* addr, float4 v) {
    atomicAdd((float4*)addr, v);
}

// ---------------- kernels ----------------
__global__ void k_init() {
    int t = blockIdx.x * blockDim.x + threadIdx.x;
    int stride = gridDim.x * blockDim.x;
    for (int i = t; i < NN * EDIM; i += stride) g_lattr[i] = 0.0f;
    for (int i = t; i < NN; i += stride) g_cnt[i] = 0.0f;
    for (int i = t; i < NN * HH; i += stride) { g_amax[i] = -CUDART_INF_F; g_denom[i] = 0.0f; }
    for (int i = t; i < NN * FF; i += stride) g_out[i] = 0.0f;
    for (int i = t; i < FF; i += stride) { g_bsum[i] = 0.0; g_bsq[i] = 0.0; }
}

// repack We[64][256] -> g_Wp[32][256] u64 over k-pairs
__global__ void k_packW(const float* __restrict__ We) {
    int t = blockIdx.x * blockDim.x + threadIdx.x;   // 8192
    int kp = t >> 8, j = t & 255;
    g_Wp[kp * HF + j] = pack2(We[(2 * kp) * HF + j], We[(2 * kp + 1) * HF + j]);
}

// x [N,64] @ W [64,256] + b, for both W_l (threads 0..63) and W_r (threads 64..127).
__global__ void k_linear(const float* __restrict__ x,
                         const float* __restrict__ Wl, const float* __restrict__ bl,
                         const float* __restrict__ Wr, const float* __restrict__ br) {
    __shared__ float sx[4 * FF];
    int row0 = blockIdx.x * 4;
    int tx = threadIdx.x;  // 128
    for (int i = tx; i < 4 * FF; i += 128) {
        int r = row0 + (i >> 6);
        sx[i] = (r < NN) ? x[r * FF + (i & 63)] : 0.0f;
    }
    __syncthreads();
    const float* W  = (tx < 64) ? Wl : Wr;
    const float* bv = (tx < 64) ? bl : br;
    float* dst      = (tx < 64) ? g_xl : g_xr;
    int j4 = (tx & 63) * 4;
    float4 bb = *(const float4*)(bv + j4);
    u64 acc[4][2];
    #pragma unroll
    for (int r = 0; r < 4; r++) { acc[r][0] = pack2(bb.x, bb.y); acc[r][1] = pack2(bb.z, bb.w); }
    #pragma unroll 4
    for (int k = 0; k < FF; k++) {
        float4 w = *(const float4*)(W + k * HF + j4);
        u64 w0 = pack2(w.x, w.y), w1 = pack2(w.z, w.w);
        #pragma unroll
        for (int r = 0; r < 4; r++) {
            u64 aa = pack2(sx[r * FF + k], sx[r * FF + k]);
            acc[r][0] = ffma2(w0, aa, acc[r][0]);
            acc[r][1] = ffma2(w1, aa, acc[r][1]);
        }
    }
    #pragma unroll
    for (int r = 0; r < 4; r++) {
        if (row0 + r < NN) {
            float2 lo = unpack2(acc[r][0]), hi = unpack2(acc[r][1]);
            *(float4*)(dst + (row0 + r) * HF + j4) = make_float4(lo.x, lo.y, hi.x, hi.y);
        }
    }
}

// segment-sum edge_attr over dst + count (16 threads/edge, float4 atomics)
__global__ void k_loopattr(const int* __restrict__ ei, const float* __restrict__ ea) {
    int t = blockIdx.x * blockDim.x + threadIdx.x;   // EE*16 threads
    int e = t >> 4, q = t & 15;
    int dst = ei[EE + e];
    float4 v = ((const float4*)ea)[e * 16 + q];
    red4(&g_lattr[dst * EDIM + q * 4], v);
    if (q == 0) atomicAdd(&g_cnt[dst], 1.0f);
}

// Per-edge: e_emb = ea @ We; m = lrelu(xl[src]+xr[dst]+e_emb); alpha[h] = <m_h, att_h>.
// Block = 128 thr (4 warps), 16 edges/block. Warp pair (g = w>>1) handles 8 edges;
// warp half (w&1) covers 128 of the 256 output columns, 4 cols/lane.
// W read from global (L1-hot) packed over k-pairs; activations LDS.64 natural pairs.
__global__ void __launch_bounds__(128, 4)
k_alpha(const int* __restrict__ ei, const float* __restrict__ ea,
        const float* __restrict__ att) {
    __shared__ u64 sEA64[16 * 32];          // 16 edges x 64 floats (viewed as 32 u64) = 4 KB
    __shared__ int sSrc[16], sDst[16];
    float* sEA = (float*)sEA64;

    int tid = threadIdx.x;
    int e0 = blockIdx.x * 16;

    if (tid < 16) {
        int e = e0 + tid;
        int s, d;
        if (e < EE) { s = ei[e]; d = ei[EE + e]; }
        else        { s = e - EE; d = e - EE; }
        sSrc[tid] = s; sDst[tid] = d;
    }
    // stage 16x64 edge attrs (self-loop rows: mean = sum/cnt folded here)
    #pragma unroll
    for (int it = 0; it < 2; it++) {
        int idx = tid + it * 128;            // 256 float4 groups
        int i = idx >> 4, g4 = idx & 15;
        int e = e0 + i;
        float4 v;
        if (e < EE) {
            v = ((const float4*)ea)[e * 16 + g4];
        } else {
            int n = e - EE;
            v = ((const float4*)g_lattr)[n * 16 + g4];
            float inv = 1.0f / fmaxf(g_cnt[n], 1.0f);
            v.x *= inv; v.y *= inv; v.z *= inv; v.w *= inv;
        }
        ((float4*)sEA)[idx] = v;
    }
    __syncthreads();

    int w = tid >> 5, lane = tid & 31;
    int g = w >> 1;                 // edge group: 8 edges
    int half = w & 1;               // column half
    int cb = half * 128 + lane * 4; // 4 scalar columns per lane

    u64 acc[8][4];
    #pragma unroll
    for (int i = 0; i < 8; i++)
        #pragma unroll
        for (int c = 0; c < 4; c++) acc[i][c] = 0ULL;

    const u64* ebase = sEA64 + g * 8 * 32;
    const u64* wbase = g_Wp + cb;

    #pragma unroll 4
    for (int kp = 0; kp < 32; kp++) {
        ulonglong2 wp0 = *(const ulonglong2*)(wbase + kp * HF);
        ulonglong2 wp1 = *(const ulonglong2*)(wbase + kp * HF + 2);
        #pragma unroll
        for (int i = 0; i < 8; i++) {
            u64 aa = ebase[i * 32 + kp];
            acc[i][0] = ffma2(wp0.x, aa, acc[i][0]);
            acc[i][1] = ffma2(wp0.y, aa, acc[i][1]);
            acc[i][2] = ffma2(wp1.x, aa, acc[i][2]);
            acc[i][3] = ffma2(wp1.y, aa, acc[i][3]);
        }
    }

    float4 attv = *(const float4*)(att + cb);

    #pragma unroll
    for (int i = 0; i < 8; i++) {
        int li = g * 8 + i;
        int e = e0 + li;
        int src = sSrc[li], dst = sDst[li];
        float4 xlv = *(const float4*)&g_xl[src * HF + cb];
        float4 xrv = *(const float4*)&g_xr[dst * HF + cb];
        float2 p0 = unpack2(acc[i][0]);
        float2 p1 = unpack2(acc[i][1]);
        float2 p2 = unpack2(acc[i][2]);
        float2 p3 = unpack2(acc[i][3]);
        float m, p = 0.0f;
        m = (p0.x + p0.y) + xlv.x + xrv.x; m = (m > 0.f) ? m : 0.2f * m; p += m * attv.x;
        m = (p1.x + p1.y) + xlv.y + xrv.y; m = (m > 0.f) ? m : 0.2f * m; p += m * attv.y;
        m = (p2.x + p2.y) + xlv.z + xrv.z; m = (m > 0.f) ? m : 0.2f * m; p += m * attv.z;
        m = (p3.x + p3.y) + xlv.w + xrv.w; m = (m > 0.f) ? m : 0.2f * m; p += m * attv.w;
        #pragma unroll
        for (int d = 1; d < 16; d <<= 1)
            p += __shfl_xor_sync(0xffffffffu, p, d);
        if (lane == 0 || lane == 16) {
            int head = 2 * half + (lane >> 4);
            g_alpha[e * HH + head] = p;
            atomicMaxF(&g_amax[dst * HH + head], p);
        }
    }
}

// exp + denominator accumulation, one thread per edge (4 heads vectorized)
__global__ void k_denom(const int* __restrict__ ei) {
    int e = blockIdx.x * blockDim.x + threadIdx.x;
    if (e >= ET) return;
    int dst = (e < EE) ? ei[EE + e] : (e - EE);
    float4 a = ((const float4*)g_alpha)[e];
    float4 mx = ((const float4*)g_amax)[dst];
    float4 ex;
    ex.x = __expf(a.x - mx.x);
    ex.y = __expf(a.y - mx.y);
    ex.z = __expf(a.z - mx.z);
    ex.w = __expf(a.w - mx.w);
    ((float4*)g_alpha)[e] = ex;
    red4(&g_denom[dst * HH], ex);
}

// 2 edges per warp (16 lanes/edge, 4 floats/lane); head-mean folded into weights.
__global__ void k_aggr(const int* __restrict__ ei) {
    int gw = (blockIdx.x * blockDim.x + threadIdx.x) >> 5;
    int lane = threadIdx.x & 31;
    int sub = lane >> 4;            // 0 or 1
    int l16 = lane & 15;
    int e = gw * 2 + sub;           // ET even -> exact coverage
    int src = (e < EE) ? ei[e] : (e - EE);
    int dst = (e < EE) ? ei[EE + e] : (e - EE);
    float wj = 0.0f;
    if (l16 < 4)
        wj = g_alpha[e * HH + l16] / (g_denom[dst * HH + l16] + 1e-16f);
    int base = sub << 4;
    float w0 = __shfl_sync(0xffffffffu, wj, base + 0);
    float w1 = __shfl_sync(0xffffffffu, wj, base + 1);
    float w2 = __shfl_sync(0xffffffffu, wj, base + 2);
    float w3 = __shfl_sync(0xffffffffu, wj, base + 3);
    int f = l16 * 4;
    const float* xb = g_xl + src * HF;
    float4 a0 = *(const float4*)(xb + 0 * 64 + f);
    float4 a1 = *(const float4*)(xb + 1 * 64 + f);
    float4 a2 = *(const float4*)(xb + 2 * 64 + f);
    float4 a3 = *(const float4*)(xb + 3 * 64 + f);
    float4 v;
    v.x = w0 * a0.x + w1 * a1.x + w2 * a2.x + w3 * a3.x;
    v.y = w0 * a0.y + w1 * a1.y + w2 * a2.y + w3 * a3.y;
    v.z = w0 * a0.z + w1 * a1.z + w2 * a2.z + w3 * a3.z;
    v.w = w0 * a0.w + w1 * a1.w + w2 * a2.w + w3 * a3.w;
    red4(&g_out[dst * FF + f], v);
}

// y = out/H + bias; accumulate BN sum/sumsq
__global__ void k_bnstat(const float* __restrict__ bias) {
    __shared__ float ss[4][64], sq[4][64];
    int f = threadIdx.x;      // 64
    int ty = threadIdx.y;     // 4
    float b = bias[f];
    float s = 0.0f, q = 0.0f;
    for (int r = blockIdx.x * 4 + ty; r < NN; r += gridDim.x * 4) {
        float y = g_out[r * FF + f] * 0.25f + b;
        g_out[r * FF + f] = y;
        s += y; q += y * y;
    }
    ss[ty][f] = s; sq[ty][f] = q;
    __syncthreads();
    if (ty == 0) {
        float S = ss[0][f] + ss[1][f] + ss[2][f] + ss[3][f];
        float Q = sq[0][f] + sq[1][f] + sq[2][f] + sq[3][f];
        atomicAdd(&g_bsum[f], (double)S);
        atomicAdd(&g_bsq[f], (double)Q);
    }
}

__global__ void k_bnfin() {
    int f = threadIdx.x;
    double m = g_bsum[f] / (double)NN;
    double v = g_bsq[f] / (double)NN - m * m;
    g_mean[f] = (float)m;
    g_istd[f] = rsqrtf((float)v + 1e-5f);
}

__global__ void k_norm(const float* __restrict__ gamma, const float* __restrict__ beta,
                       float* __restrict__ out) {
    int t = blockIdx.x * blockDim.x + threadIdx.x;
    if (t >= NN * FF) return;
    int f = t & 63;
    float y = (g_out[t] - g_mean[f]) * g_istd[f] * gamma[f] + beta[f];
    out[t] = fmaxf(y, 0.0f);
}

// ---------------- launch ----------------
extern "C" void kernel_launch(void* const* d_in, const int* in_sizes, int n_in,
                              void* d_out, int out_size) {
    const float* x     = (const float*)d_in[0];
    const int*   ei    = (const int*)d_in[1];
    const float* ea    = (const float*)d_in[2];
    const float* Wl    = (const float*)d_in[3];
    const float* bl    = (const float*)d_in[4];
    const float* Wr    = (const float*)d_in[5];
    const float* br    = (const float*)d_in[6];
    const float* We    = (const float*)d_in[7];
    const float* att   = (const float*)d_in[8];
    const float* bias  = (const float*)d_in[9];
    const float* gamma = (const float*)d_in[10];
    const float* beta  = (const float*)d_in[11];
    float* out = (float*)d_out;

    k_init<<<4096, 256>>>();
    k_packW<<<32, 256>>>(We);
    k_linear<<<(NN + 3) / 4, 128>>>(x, Wl, bl, Wr, br);
    k_loopattr<<<(EE * 16) / 256, 256>>>(ei, ea);
    k_alpha<<<ET / 16, 128>>>(ei, ea, att);
    k_denom<<<(ET + 255) / 256, 256>>>(ei);
    k_aggr<<<(ET / 2 * 32) / 256, 256>>>(ei);
    k_bnstat<<<256, dim3(64, 4)>>>(bias);
    k_bnfin<<<1, 64>>>();
    k_norm<<<(NN * FF + 255) / 256, 256>>>(gamma, beta, out);
}